// round 5
// baseline (speedup 1.0000x reference)
#include <cuda_runtime.h>

#define Nn   64
#define Cc   256
#define HWs  3136
#define Gg   16
#define CGc  16
#define Mf   200704.0f
#define EPSf 1e-3f
#define NACC 152       // 16 sums + 136 upper-tri products
#define SBLK 9         // hw-chunks per group in k_stats
#define CHUNK 22304    // ceil(200704/9) rounded to multiple of 4

#define HW4       784              // float4 columns per (n, channel) row
#define TOT_TASKS (Nn * Gg * HW4)  // 802816 float4-column tasks
#define APPLY_BLOCKS 740           // 148 SMs x occupancy 5 (128-thr blocks)

// Scratch (static device globals — no allocation)
__device__ float g_part[Gg][SBLK][NACC];
__device__ float g_A[Gg][16][16];           // weight * wm   (A[g][c][d])
__device__ float g_beta[Gg][16];            // bias - A*mean

// ---------------------------------------------------------------------------
// Kernel 1: per-group channel sums + Gram partials. Grid (16, SBLK), 256 thr.
// float2 positions with explicit double-buffered prefetch: next iteration's
// 16 LDG.64 issue before the current FMA block, hiding DRAM latency at occ 1.
// ---------------------------------------------------------------------------
__global__ __launch_bounds__(256, 1) void k_stats(const float* __restrict__ X) {
    const int g = blockIdx.x, b = blockIdx.y;
    const int start = b * CHUNK;
    const int end   = (start + CHUNK < Nn * HWs) ? (start + CHUNK) : (Nn * HWs);
    const float* gbase = X + (size_t)g * CGc * HWs;

    float s[16];
    float p[136];
#pragma unroll
    for (int i = 0; i < 16; i++) s[i] = 0.f;
#pragma unroll
    for (int i = 0; i < 136; i++) p[i] = 0.f;

    int ppos = start + 2 * threadIdx.x;
    float2 nb[16];
    if (ppos < end) {
        const int n  = ppos / HWs;
        const int hw = ppos - n * HWs;      // even, never straddles a row
        const float* rowb = gbase + (size_t)n * Cc * HWs + hw;
#pragma unroll
        for (int c = 0; c < 16; c++)
            nb[c] = *(const float2*)(rowb + c * HWs);
    }

    while (ppos < end) {
        float2 v[16];
#pragma unroll
        for (int c = 0; c < 16; c++) v[c] = nb[c];

        const int nxt = ppos + 512;         // 256 threads * 2 floats
        if (nxt < end) {
            const int n  = nxt / HWs;
            const int hw = nxt - n * HWs;
            const float* rowb = gbase + (size_t)n * Cc * HWs + hw;
#pragma unroll
            for (int c = 0; c < 16; c++)
                nb[c] = *(const float2*)(rowb + c * HWs);
        }

#pragma unroll
        for (int c = 0; c < 16; c++)
            s[c] += v[c].x + v[c].y;

        int idx = 0;
#pragma unroll
        for (int i = 0; i < 16; i++)
#pragma unroll
            for (int j = i; j < 16; j++) {
                float a = p[idx];
                a = fmaf(v[i].x, v[j].x, a);
                a = fmaf(v[i].y, v[j].y, a);
                p[idx] = a;
                idx++;
            }

        ppos = nxt;
    }

    // intra-warp tree reduction
#pragma unroll
    for (int off = 16; off > 0; off >>= 1) {
#pragma unroll
        for (int i = 0; i < 16; i++)  s[i] += __shfl_down_sync(0xffffffffu, s[i], off);
#pragma unroll
        for (int i = 0; i < 136; i++) p[i] += __shfl_down_sync(0xffffffffu, p[i], off);
    }

    __shared__ float red[8][NACC];
    const int warp = threadIdx.x >> 5, lane = threadIdx.x & 31;
    if (lane == 0) {
#pragma unroll
        for (int i = 0; i < 16; i++)  red[warp][i]      = s[i];
#pragma unroll
        for (int i = 0; i < 136; i++) red[warp][16 + i] = p[i];
    }
    __syncthreads();
    for (int t = threadIdx.x; t < NACC; t += 256) {
        float a = 0.f;
#pragma unroll
        for (int w = 0; w < 8; w++) a += red[w][t];
        g_part[g][b][t] = a;
    }
}

// ---------------------------------------------------------------------------
// Kernel 2: reduce partials -> sigma -> Newton-Schulz Sigma^{-1/2} -> fold
// weight/bias/mean into A = w*wm, beta = b - A*mean. 16 blocks x 256 threads.
// ---------------------------------------------------------------------------
__global__ __launch_bounds__(256, 1) void k_wm(const float* __restrict__ wgt,
                                               const float* __restrict__ bia) {
    const int g = blockIdx.x;
    const int t = threadIdx.x;

    __shared__ float S[NACC];
    __shared__ float meanS[16];
    __shared__ float sig[16][17], P[16][17], T1[16][17], T2[16][17];

    if (t < NACC) {
        float a = 0.f;
#pragma unroll
        for (int ch = 0; ch < SBLK; ch++) a += g_part[g][ch][t];
        S[t] = a;
    }
    __syncthreads();
    if (t < 16) meanS[t] = S[t] * (1.0f / Mf);
    __syncthreads();

    const int r = t >> 4, c = t & 15;
    const int i = (r < c) ? r : c;
    const int j = (r < c) ? c : r;
    const int pidx = 16 + i * 16 - (i * (i - 1)) / 2 + (j - i);
    float sv = S[pidx] * (1.0f / Mf) - meanS[r] * meanS[c] + ((r == c) ? EPSf : 0.f);
    sig[r][c] = sv;
    __syncthreads();

    float tr = 0.f;
#pragma unroll
    for (int k = 0; k < 16; k++) tr += sig[k][k];
    __syncthreads();

    sig[r][c] = sv / tr;                 // Sigma_N
    P[r][c] = (r == c) ? 1.f : 0.f;
    __syncthreads();

    for (int it = 0; it < 10; it++) {
        float d1 = 0.f;
#pragma unroll
        for (int k = 0; k < 16; k++) d1 += P[r][k] * P[k][c];
        T1[r][c] = d1;
        __syncthreads();
        float d2 = 0.f;
#pragma unroll
        for (int k = 0; k < 16; k++) d2 += T1[r][k] * P[k][c];
        T2[r][c] = d2;
        __syncthreads();
        float d3 = 0.f;
#pragma unroll
        for (int k = 0; k < 16; k++) d3 += T2[r][k] * sig[k][c];
        P[r][c] = 1.5f * P[r][c] - 0.5f * d3;
        __syncthreads();
    }

    const float wmv = P[r][c] * rsqrtf(tr);      // Sigma^{-1/2}
    const float Av  = wgt[g * 16 + r] * wmv;
    g_A[g][r][c] = Av;
    T1[r][c] = Av * meanS[c];
    __syncthreads();
    if (t < 16) {
        float acc = bia[g * 16 + t];
#pragma unroll
        for (int d = 0; d < 16; d++) acc -= T1[t][d];
        g_beta[g][t] = acc;
    }
}

// ---------------------------------------------------------------------------
// Kernel 3: apply out = A*v + beta. Persistent single-wave grid, 128-thread
// blocks at occupancy 5 (20 warps/SM). All 16 groups' A/beta in smem.
// ---------------------------------------------------------------------------
__global__ __launch_bounds__(128, 5) void k_apply(const float* __restrict__ X,
                                                  float* __restrict__ Y) {
    __shared__ float As[Gg * 256];   // As[g*256 + c*16 + d]
    __shared__ float Bs[Gg * 16];    // Bs[g*16 + c]

    for (int i = threadIdx.x; i < Gg * 256; i += 128)
        As[i] = ((const float*)g_A)[i];
    for (int i = threadIdx.x; i < Gg * 16; i += 128)
        Bs[i] = ((const float*)g_beta)[i];
    __syncthreads();

    const int stride = APPLY_BLOCKS * 128;
    for (int t = blockIdx.x * 128 + threadIdx.x; t < TOT_TASKS; t += stride) {
        const int col = t / HW4;          // n*16 + g
        const int q   = t - col * HW4;    // hw4
        const int g   = col & 15;
        const int n   = col >> 4;

        const size_t off = ((size_t)n * Cc + (size_t)g * CGc) * HWs;
        const float4* xb = (const float4*)(X + off) + q;
        float4*       yb = (float4*)(Y + off) + q;
        const float*  Ag = As + g * 256;
        const float*  Bg = Bs + g * 16;

        float4 acc[16];
#pragma unroll
        for (int c = 0; c < 16; c++) {
            const float b = Bg[c];
            acc[c].x = b; acc[c].y = b; acc[c].z = b; acc[c].w = b;
        }

#pragma unroll
        for (int d = 0; d < 16; d++) {
            const float4 xv = xb[d * HW4];
#pragma unroll
            for (int c = 0; c < 16; c++) {
                const float w = Ag[c * 16 + d];
                acc[c].x = fmaf(w, xv.x, acc[c].x);
                acc[c].y = fmaf(w, xv.y, acc[c].y);
                acc[c].z = fmaf(w, xv.z, acc[c].z);
                acc[c].w = fmaf(w, xv.w, acc[c].w);
            }
        }
#pragma unroll
        for (int c = 0; c < 16; c++)
            yb[c * HW4] = acc[c];
    }
}

// ---------------------------------------------------------------------------
extern "C" void kernel_launch(void* const* d_in, const int* in_sizes, int n_in,
                              void* d_out, int out_size) {
    const float* X = (const float*)d_in[0];
    const float* W = (const float*)d_in[1];
    const float* B = (const float*)d_in[2];
    float* Y = (float*)d_out;

    k_stats<<<dim3(Gg, SBLK), 256>>>(X);
    k_wm<<<Gg, 256>>>(W, B);
    k_apply<<<APPLY_BLOCKS, 128>>>(X, Y);
}

// round 6
// speedup vs baseline: 1.0583x; 1.0583x over previous
#include <cuda_runtime.h>

#define Nn   64
#define Cc   256
#define HWs  3136
#define Gg   16
#define CGc  16
#define Mf   200704.0f
#define EPSf 1e-3f
#define NACC 152       // 16 sums + 136 upper-tri products
#define SBLK 8         // blocks per group in k_stats
#define NTILE 98       // tiles per block (784 total / 8)

#define HW4       784              // float4 columns per (n, channel) row
#define TOT_TASKS (Nn * Gg * HW4)  // 802816 float4-column tasks
#define APPLY_BLOCKS 296           // 148 SMs x occupancy 2 = one wave

// Scratch (static device globals — no allocation)
__device__ float g_part[Gg][SBLK][NACC];
__device__ float g_A[Gg][16][16];           // weight * wm   (A[g][c][d])
__device__ float g_beta[Gg][16];            // bias - A*mean

// ---------------------------------------------------------------------------
// Kernel 1: per-group channel sums + Gram partials, cp.async smem-staged.
// Grid (16, 8), 256 threads. Tile = 16ch x 256 positions (16 KB), double
// buffered. Loads have no register destination -> FMA block never waits on
// a load scoreboard; pipeline hides DRAM latency at occupancy 1.
// ---------------------------------------------------------------------------
__global__ __launch_bounds__(256, 1) void k_stats(const float* __restrict__ X) {
    const int g = blockIdx.x, b = blockIdx.y;
    const int t = threadIdx.x;
    const float* gbase = X + (size_t)g * CGc * HWs;

    __shared__ float buf[2][16 * 256];     // [buf][ch*256 + pos]

    float s[16];
    float p[136];
#pragma unroll
    for (int i = 0; i < 16; i++) s[i] = 0.f;
#pragma unroll
    for (int i = 0; i < 136; i++) p[i] = 0.f;

    const int tile0 = b * NTILE;

    // prefetch lambda-equivalent via macro-ish inline
#define PREFETCH(TILE, BUFI)                                                   \
    {                                                                          \
        const int _tile = (TILE);                                              \
        const int _bi = (BUFI);                                                \
        _Pragma("unroll")                                                      \
        for (int j = 0; j < 4; j++) {                                          \
            const int seg  = t + 256 * j;                                      \
            const int ch   = seg >> 6;                                         \
            const int quad = seg & 63;                                         \
            const int ppos = _tile * 256 + quad * 4;                           \
            const int n    = ppos / HWs;                                       \
            const int hw   = ppos - n * HWs;                                   \
            const float* src = gbase + (size_t)n * Cc * HWs +                  \
                               (size_t)ch * HWs + hw;                          \
            unsigned dst = (unsigned)__cvta_generic_to_shared(                 \
                &buf[_bi][ch * 256 + quad * 4]);                               \
            asm volatile("cp.async.cg.shared.global [%0], [%1], 16;"           \
                         :: "r"(dst), "l"(src));                               \
        }                                                                      \
        asm volatile("cp.async.commit_group;");                                \
    }

    PREFETCH(tile0, 0);

    for (int k = 0; k < NTILE; k++) {
        if (k + 1 < NTILE) {
            PREFETCH(tile0 + k + 1, (k + 1) & 1);
            asm volatile("cp.async.wait_group 1;");
        } else {
            asm volatile("cp.async.wait_group 0;");
        }
        __syncthreads();

        const float* bb = buf[k & 1];
        float v[16];
#pragma unroll
        for (int c = 0; c < 16; c++) v[c] = bb[c * 256 + t];

#pragma unroll
        for (int c = 0; c < 16; c++) s[c] += v[c];

        int idx = 0;
#pragma unroll
        for (int i = 0; i < 16; i++)
#pragma unroll
            for (int j = i; j < 16; j++) {
                p[idx] = fmaf(v[i], v[j], p[idx]);
                idx++;
            }
        __syncthreads();   // compute done before this buffer is overwritten
    }
#undef PREFETCH

    // intra-warp tree reduction
#pragma unroll
    for (int off = 16; off > 0; off >>= 1) {
#pragma unroll
        for (int i = 0; i < 16; i++)  s[i] += __shfl_down_sync(0xffffffffu, s[i], off);
#pragma unroll
        for (int i = 0; i < 136; i++) p[i] += __shfl_down_sync(0xffffffffu, p[i], off);
    }

    // cross-warp reduction, reusing buf[0] as scratch
    float* red = &buf[0][0];   // needs 8*152 floats < 4096
    const int warp = t >> 5, lane = t & 31;
    if (lane == 0) {
#pragma unroll
        for (int i = 0; i < 16; i++)  red[warp * NACC + i]      = s[i];
#pragma unroll
        for (int i = 0; i < 136; i++) red[warp * NACC + 16 + i] = p[i];
    }
    __syncthreads();
    for (int i = t; i < NACC; i += 256) {
        float a = 0.f;
#pragma unroll
        for (int w = 0; w < 8; w++) a += red[w * NACC + i];
        g_part[g][b][i] = a;
    }
}

// ---------------------------------------------------------------------------
// Kernel 2: reduce partials -> sigma -> Newton-Schulz Sigma^{-1/2} -> fold
// weight/bias/mean into A = w*wm, beta = b - A*mean. 16 blocks x 256 threads.
// ---------------------------------------------------------------------------
__global__ __launch_bounds__(256, 1) void k_wm(const float* __restrict__ wgt,
                                               const float* __restrict__ bia) {
    const int g = blockIdx.x;
    const int t = threadIdx.x;

    __shared__ float S[NACC];
    __shared__ float meanS[16];
    __shared__ float sig[16][17], P[16][17], T1[16][17], T2[16][17];

    if (t < NACC) {
        float a = 0.f;
#pragma unroll
        for (int ch = 0; ch < SBLK; ch++) a += g_part[g][ch][t];
        S[t] = a;
    }
    __syncthreads();
    if (t < 16) meanS[t] = S[t] * (1.0f / Mf);
    __syncthreads();

    const int r = t >> 4, c = t & 15;
    const int i = (r < c) ? r : c;
    const int j = (r < c) ? c : r;
    const int pidx = 16 + i * 16 - (i * (i - 1)) / 2 + (j - i);
    float sv = S[pidx] * (1.0f / Mf) - meanS[r] * meanS[c] + ((r == c) ? EPSf : 0.f);
    sig[r][c] = sv;
    __syncthreads();

    float tr = 0.f;
#pragma unroll
    for (int k = 0; k < 16; k++) tr += sig[k][k];
    __syncthreads();

    sig[r][c] = sv / tr;                 // Sigma_N
    P[r][c] = (r == c) ? 1.f : 0.f;
    __syncthreads();

    for (int it = 0; it < 10; it++) {
        float d1 = 0.f;
#pragma unroll
        for (int k = 0; k < 16; k++) d1 += P[r][k] * P[k][c];
        T1[r][c] = d1;
        __syncthreads();
        float d2 = 0.f;
#pragma unroll
        for (int k = 0; k < 16; k++) d2 += T1[r][k] * P[k][c];
        T2[r][c] = d2;
        __syncthreads();
        float d3 = 0.f;
#pragma unroll
        for (int k = 0; k < 16; k++) d3 += T2[r][k] * sig[k][c];
        P[r][c] = 1.5f * P[r][c] - 0.5f * d3;
        __syncthreads();
    }

    const float wmv = P[r][c] * rsqrtf(tr);      // Sigma^{-1/2}
    const float Av  = wgt[g * 16 + r] * wmv;
    g_A[g][r][c] = Av;
    T1[r][c] = Av * meanS[c];
    __syncthreads();
    if (t < 16) {
        float acc = bia[g * 16 + t];
#pragma unroll
        for (int d = 0; d < 16; d++) acc -= T1[t][d];
        g_beta[g][t] = acc;
    }
}

// ---------------------------------------------------------------------------
// Kernel 3: apply out = A*v + beta. Persistent single-wave grid (296 blocks,
// 256 threads, occ 2) — the R4 configuration (measured best: ~71 us).
// ---------------------------------------------------------------------------
__global__ __launch_bounds__(256, 2) void k_apply(const float* __restrict__ X,
                                                  float* __restrict__ Y) {
    __shared__ float As[Gg * 256];   // As[g*256 + c*16 + d]
    __shared__ float Bs[Gg * 16];    // Bs[g*16 + c]

    for (int i = threadIdx.x; i < Gg * 256; i += 256)
        As[i] = ((const float*)g_A)[i];
    Bs[threadIdx.x] = ((const float*)g_beta)[threadIdx.x];
    __syncthreads();

    const int stride = APPLY_BLOCKS * 256;
    for (int t = blockIdx.x * 256 + threadIdx.x; t < TOT_TASKS; t += stride) {
        const int col = t / HW4;          // n*16 + g
        const int q   = t - col * HW4;    // hw4
        const int g   = col & 15;
        const int n   = col >> 4;

        const size_t off = ((size_t)n * Cc + (size_t)g * CGc) * HWs;
        const float4* xb = (const float4*)(X + off) + q;
        float4*       yb = (float4*)(Y + off) + q;
        const float*  Ag = As + g * 256;
        const float*  Bg = Bs + g * 16;

        float4 acc[16];
#pragma unroll
        for (int c = 0; c < 16; c++) {
            const float b = Bg[c];
            acc[c].x = b; acc[c].y = b; acc[c].z = b; acc[c].w = b;
        }

#pragma unroll
        for (int d = 0; d < 16; d++) {
            const float4 xv = xb[d * HW4];
#pragma unroll
            for (int c = 0; c < 16; c++) {
                const float w = Ag[c * 16 + d];
                acc[c].x = fmaf(w, xv.x, acc[c].x);
                acc[c].y = fmaf(w, xv.y, acc[c].y);
                acc[c].z = fmaf(w, xv.z, acc[c].z);
                acc[c].w = fmaf(w, xv.w, acc[c].w);
            }
        }
#pragma unroll
        for (int c = 0; c < 16; c++)
            yb[c * HW4] = acc[c];
    }
}

// ---------------------------------------------------------------------------
extern "C" void kernel_launch(void* const* d_in, const int* in_sizes, int n_in,
                              void* d_out, int out_size) {
    const float* X = (const float*)d_in[0];
    const float* W = (const float*)d_in[1];
    const float* B = (const float*)d_in[2];
    float* Y = (float*)d_out;

    k_stats<<<dim3(Gg, SBLK), 256>>>(X);
    k_wm<<<Gg, 256>>>(W, B);
    k_apply<<<APPLY_BLOCKS, 256>>>(X, Y);
}

// round 7
// speedup vs baseline: 1.0598x; 1.0014x over previous
#include <cuda_runtime.h>

#define Nn   64
#define Cc   256
#define HWs  3136
#define Gg   16
#define CGc  16
#define Mf   200704.0f
#define EPSf 1e-3f
#define NACC 152       // 16 sums + 136 upper-tri products
#define SBLK 8         // blocks per group in k_stats
#define NTILE 98       // tiles per block (784 total / 8)

#define HW4       784              // float4 columns per (n, channel) row
#define TOT_TASKS (Nn * Gg * HW4)  // 802816 float4-column tasks
#define APPLY_BLOCKS 296           // 148 SMs x occupancy 2 = one wave

// Scratch (static device globals — no allocation)
__device__ float g_part[Gg][SBLK][NACC];
__device__ float g_A[Gg][16][16];           // weight * wm   (A[g][c][d])
__device__ float g_beta[Gg][16];            // bias - A*mean

// ---------------------------------------------------------------------------
// Kernel 1: per-group channel sums + Gram partials, cp.async smem-staged.
// Grid (16, 8), 256 threads. Tile = 16ch x 256 positions (16 KB), double
// buffered. Loads have no register destination -> FMA block never waits on
// a load scoreboard; pipeline hides DRAM latency at occupancy 1.
// ---------------------------------------------------------------------------
__global__ __launch_bounds__(256, 1) void k_stats(const float* __restrict__ X) {
    const int g = blockIdx.x, b = blockIdx.y;
    const int t = threadIdx.x;
    const float* gbase = X + (size_t)g * CGc * HWs;

    __shared__ float buf[2][16 * 256];     // [buf][ch*256 + pos]

    float s[16];
    float p[136];
#pragma unroll
    for (int i = 0; i < 16; i++) s[i] = 0.f;
#pragma unroll
    for (int i = 0; i < 136; i++) p[i] = 0.f;

    const int tile0 = b * NTILE;

    // prefetch lambda-equivalent via macro-ish inline
#define PREFETCH(TILE, BUFI)                                                   \
    {                                                                          \
        const int _tile = (TILE);                                              \
        const int _bi = (BUFI);                                                \
        _Pragma("unroll")                                                      \
        for (int j = 0; j < 4; j++) {                                          \
            const int seg  = t + 256 * j;                                      \
            const int ch   = seg >> 6;                                         \
            const int quad = seg & 63;                                         \
            const int ppos = _tile * 256 + quad * 4;                           \
            const int n    = ppos / HWs;                                       \
            const int hw   = ppos - n * HWs;                                   \
            const float* src = gbase + (size_t)n * Cc * HWs +                  \
                               (size_t)ch * HWs + hw;                          \
            unsigned dst = (unsigned)__cvta_generic_to_shared(                 \
                &buf[_bi][ch * 256 + quad * 4]);                               \
            asm volatile("cp.async.cg.shared.global [%0], [%1], 16;"           \
                         :: "r"(dst), "l"(src));                               \
        }                                                                      \
        asm volatile("cp.async.commit_group;");                                \
    }

    PREFETCH(tile0, 0);

    for (int k = 0; k < NTILE; k++) {
        if (k + 1 < NTILE) {
            PREFETCH(tile0 + k + 1, (k + 1) & 1);
            asm volatile("cp.async.wait_group 1;");
        } else {
            asm volatile("cp.async.wait_group 0;");
        }
        __syncthreads();

        const float* bb = buf[k & 1];
        float v[16];
#pragma unroll
        for (int c = 0; c < 16; c++) v[c] = bb[c * 256 + t];

#pragma unroll
        for (int c = 0; c < 16; c++) s[c] += v[c];

        int idx = 0;
#pragma unroll
        for (int i = 0; i < 16; i++)
#pragma unroll
            for (int j = i; j < 16; j++) {
                p[idx] = fmaf(v[i], v[j], p[idx]);
                idx++;
            }
        __syncthreads();   // compute done before this buffer is overwritten
    }
#undef PREFETCH

    // intra-warp tree reduction
#pragma unroll
    for (int off = 16; off > 0; off >>= 1) {
#pragma unroll
        for (int i = 0; i < 16; i++)  s[i] += __shfl_down_sync(0xffffffffu, s[i], off);
#pragma unroll
        for (int i = 0; i < 136; i++) p[i] += __shfl_down_sync(0xffffffffu, p[i], off);
    }

    // cross-warp reduction, reusing buf[0] as scratch
    float* red = &buf[0][0];   // needs 8*152 floats < 4096
    const int warp = t >> 5, lane = t & 31;
    if (lane == 0) {
#pragma unroll
        for (int i = 0; i < 16; i++)  red[warp * NACC + i]      = s[i];
#pragma unroll
        for (int i = 0; i < 136; i++) red[warp * NACC + 16 + i] = p[i];
    }
    __syncthreads();
    for (int i = t; i < NACC; i += 256) {
        float a = 0.f;
#pragma unroll
        for (int w = 0; w < 8; w++) a += red[w * NACC + i];
        g_part[g][b][i] = a;
    }
}

// ---------------------------------------------------------------------------
// Kernel 2: reduce partials -> sigma -> Newton-Schulz Sigma^{-1/2} -> fold
// weight/bias/mean into A = w*wm, beta = b - A*mean. 16 blocks x 256 threads.
// ---------------------------------------------------------------------------
__global__ __launch_bounds__(256, 1) void k_wm(const float* __restrict__ wgt,
                                               const float* __restrict__ bia) {
    const int g = blockIdx.x;
    const int t = threadIdx.x;

    __shared__ float S[NACC];
    __shared__ float meanS[16];
    __shared__ float sig[16][17], P[16][17], T1[16][17], T2[16][17];

    if (t < NACC) {
        float a = 0.f;
#pragma unroll
        for (int ch = 0; ch < SBLK; ch++) a += g_part[g][ch][t];
        S[t] = a;
    }
    __syncthreads();
    if (t < 16) meanS[t] = S[t] * (1.0f / Mf);
    __syncthreads();

    const int r = t >> 4, c = t & 15;
    const int i = (r < c) ? r : c;
    const int j = (r < c) ? c : r;
    const int pidx = 16 + i * 16 - (i * (i - 1)) / 2 + (j - i);
    float sv = S[pidx] * (1.0f / Mf) - meanS[r] * meanS[c] + ((r == c) ? EPSf : 0.f);
    sig[r][c] = sv;
    __syncthreads();

    float tr = 0.f;
#pragma unroll
    for (int k = 0; k < 16; k++) tr += sig[k][k];
    __syncthreads();

    sig[r][c] = sv / tr;                 // Sigma_N
    P[r][c] = (r == c) ? 1.f : 0.f;
    __syncthreads();

    for (int it = 0; it < 10; it++) {
        float d1 = 0.f;
#pragma unroll
        for (int k = 0; k < 16; k++) d1 += P[r][k] * P[k][c];
        T1[r][c] = d1;
        __syncthreads();
        float d2 = 0.f;
#pragma unroll
        for (int k = 0; k < 16; k++) d2 += T1[r][k] * P[k][c];
        T2[r][c] = d2;
        __syncthreads();
        float d3 = 0.f;
#pragma unroll
        for (int k = 0; k < 16; k++) d3 += T2[r][k] * sig[k][c];
        P[r][c] = 1.5f * P[r][c] - 0.5f * d3;
        __syncthreads();
    }

    const float wmv = P[r][c] * rsqrtf(tr);      // Sigma^{-1/2}
    const float Av  = wgt[g * 16 + r] * wmv;
    g_A[g][r][c] = Av;
    T1[r][c] = Av * meanS[c];
    __syncthreads();
    if (t < 16) {
        float acc = bia[g * 16 + t];
#pragma unroll
        for (int d = 0; d < 16; d++) acc -= T1[t][d];
        g_beta[g][t] = acc;
    }
}

// ---------------------------------------------------------------------------
// Kernel 3: apply out = A*v + beta. Persistent single-wave grid (296 blocks,
// 256 threads, occ 2) — the R4 configuration (measured best: ~71 us).
// ---------------------------------------------------------------------------
__global__ __launch_bounds__(256, 2) void k_apply(const float* __restrict__ X,
                                                  float* __restrict__ Y) {
    __shared__ float As[Gg * 256];   // As[g*256 + c*16 + d]
    __shared__ float Bs[Gg * 16];    // Bs[g*16 + c]

    for (int i = threadIdx.x; i < Gg * 256; i += 256)
        As[i] = ((const float*)g_A)[i];
    Bs[threadIdx.x] = ((const float*)g_beta)[threadIdx.x];
    __syncthreads();

    const int stride = APPLY_BLOCKS * 256;
    for (int t = blockIdx.x * 256 + threadIdx.x; t < TOT_TASKS; t += stride) {
        const int col = t / HW4;          // n*16 + g
        const int q   = t - col * HW4;    // hw4
        const int g   = col & 15;
        const int n   = col >> 4;

        const size_t off = ((size_t)n * Cc + (size_t)g * CGc) * HWs;
        const float4* xb = (const float4*)(X + off) + q;
        float4*       yb = (float4*)(Y + off) + q;
        const float*  Ag = As + g * 256;
        const float*  Bg = Bs + g * 16;

        float4 acc[16];
#pragma unroll
        for (int c = 0; c < 16; c++) {
            const float b = Bg[c];
            acc[c].x = b; acc[c].y = b; acc[c].z = b; acc[c].w = b;
        }

#pragma unroll
        for (int d = 0; d < 16; d++) {
            const float4 xv = xb[d * HW4];
#pragma unroll
            for (int c = 0; c < 16; c++) {
                const float w = Ag[c * 16 + d];
                acc[c].x = fmaf(w, xv.x, acc[c].x);
                acc[c].y = fmaf(w, xv.y, acc[c].y);
                acc[c].z = fmaf(w, xv.z, acc[c].z);
                acc[c].w = fmaf(w, xv.w, acc[c].w);
            }
        }
#pragma unroll
        for (int c = 0; c < 16; c++)
            yb[c * HW4] = acc[c];
    }
}

// ---------------------------------------------------------------------------
extern "C" void kernel_launch(void* const* d_in, const int* in_sizes, int n_in,
                              void* d_out, int out_size) {
    const float* X = (const float*)d_in[0];
    const float* W = (const float*)d_in[1];
    const float* B = (const float*)d_in[2];
    float* Y = (float*)d_out;

    k_stats<<<dim3(Gg, SBLK), 256>>>(X);
    k_wm<<<Gg, 256>>>(W, B);
    k_apply<<<APPLY_BLOCKS, 256>>>(X, Y);
}

// round 11
// speedup vs baseline: 1.2623x; 1.1911x over previous
#include <cuda_runtime.h>
#include <cstdint>

#define Nn   64
#define Cc   256
#define HWs  3136
#define Gg   16
#define Mf   200704.0f
#define EPSf 1e-3f

#define SLICES 148                 // one slice per block, one wave
#define HW4       784
#define TOT_TASKS (Nn * Gg * HW4)
#define APPLY_BLOCKS 296

// Scratch (static device globals — no allocation)
__device__ float g_sig[Gg][SLICES][16][16];  // per-slice Gram partials
__device__ float g_sum[Gg][SLICES][16];      // per-slice channel sums
__device__ float g_A[Gg][16][16];            // weight * wm
__device__ float g_beta[Gg][16];             // bias - A*mean

// ---------------- helpers ----------------
__device__ __forceinline__ uint32_t to_tf32(float f) {
    uint32_t u;
    asm("cvt.rna.tf32.f32 %0, %1;" : "=r"(u) : "f"(f));
    return u;
}

__device__ __forceinline__ void mma_tf32(float* c, uint32_t a0, uint32_t a1,
                                         uint32_t a2, uint32_t a3,
                                         uint32_t b0, uint32_t b1) {
    asm("mma.sync.aligned.m16n8k8.row.col.f32.tf32.tf32.f32 "
        "{%0,%1,%2,%3}, {%4,%5,%6,%7}, {%8,%9}, {%0,%1,%2,%3};"
        : "+f"(c[0]), "+f"(c[1]), "+f"(c[2]), "+f"(c[3])
        : "r"(a0), "r"(a1), "r"(a2), "r"(a3), "r"(b0), "r"(b1));
}

// ---------------------------------------------------------------------------
// Kernel 1: Gram via warp-level tf32 mma.sync (D = X X^T per group) + channel
// sums. Grid 148 x 512 (one wave). Block = position-slice, warp = group.
// B fragments alias A fragments, so each 16-position step is just
// 2x LDG.128 + 8x cvt.tf32 + 4x mma. 64-position units, 8 LDG in flight.
// ---------------------------------------------------------------------------
__global__ __launch_bounds__(512, 1) void k_stats(const float* __restrict__ X) {
    const int s = blockIdx.x;                 // slice
    const int g = threadIdx.x >> 5;           // warp = group
    const int lane = threadIdx.x & 31;
    const int row = lane >> 2, q = lane & 3;

    // slice s covers 64-position units; first 28 slices get 22 units, rest 21.
    const int units = 21 + (s < 28 ? 1 : 0);
    int p = s * 1344 + (s < 28 ? s : 28) * 64;

    float c[8];                                // c[0..3]=cols(2q,2q+1) rows(row,row+8); c[4..7]=cols+8
#pragma unroll
    for (int i = 0; i < 8; i++) c[i] = 0.f;
    float slo = 0.f, shi = 0.f;

    const float* gb = X + (size_t)(g * 16 + row) * HWs + 4 * q;

    for (int u = 0; u < units; u++, p += 64) {
        const int n  = p / HWs;
        const int hw = p - n * HWs;            // multiple of 64
        const float* b0 = gb + (size_t)n * Cc * HWs + hw;
        const float* b1 = b0 + 8 * HWs;

        float4 vlo[4], vhi[4];
#pragma unroll
        for (int i = 0; i < 4; i++) vlo[i] = *(const float4*)(b0 + 16 * i);
#pragma unroll
        for (int i = 0; i < 4; i++) vhi[i] = *(const float4*)(b1 + 16 * i);

#pragma unroll
        for (int i = 0; i < 4; i++) {
            slo += (vlo[i].x + vlo[i].y) + (vlo[i].z + vlo[i].w);
            shi += (vhi[i].x + vhi[i].y) + (vhi[i].z + vhi[i].w);

            // chunk 0: positions v.x (k-slot q), v.y (k-slot q+4)
            uint32_t a0 = to_tf32(vlo[i].x), a1 = to_tf32(vhi[i].x);
            uint32_t a2 = to_tf32(vlo[i].y), a3 = to_tf32(vhi[i].y);
            mma_tf32(c,     a0, a1, a2, a3, a0, a2);   // cols 0..7
            mma_tf32(c + 4, a0, a1, a2, a3, a1, a3);   // cols 8..15

            // chunk 1: positions v.z, v.w
            uint32_t e0 = to_tf32(vlo[i].z), e1 = to_tf32(vhi[i].z);
            uint32_t e2 = to_tf32(vlo[i].w), e3 = to_tf32(vhi[i].w);
            mma_tf32(c,     e0, e1, e2, e3, e0, e2);
            mma_tf32(c + 4, e0, e1, e2, e3, e1, e3);
        }
    }

    // channel sums: reduce across the 4 q-lanes sharing a row
    slo += __shfl_xor_sync(0xffffffffu, slo, 1);
    slo += __shfl_xor_sync(0xffffffffu, slo, 2);
    shi += __shfl_xor_sync(0xffffffffu, shi, 1);
    shi += __shfl_xor_sync(0xffffffffu, shi, 2);
    if (q == 0) {
        g_sum[g][s][row]     = slo;
        g_sum[g][s][row + 8] = shi;
    }

    // write Gram partial (fragment layout: c0/c1 cols 2q,2q+1 row=row; c2/c3 row+8)
    float2 f01 = make_float2(c[0], c[1]);
    float2 f23 = make_float2(c[2], c[3]);
    float2 f45 = make_float2(c[4], c[5]);
    float2 f67 = make_float2(c[6], c[7]);
    *(float2*)&g_sig[g][s][row][2 * q]         = f01;
    *(float2*)&g_sig[g][s][row + 8][2 * q]     = f23;
    *(float2*)&g_sig[g][s][row][8 + 2 * q]     = f45;
    *(float2*)&g_sig[g][s][row + 8][8 + 2 * q] = f67;
}

// ---------------------------------------------------------------------------
// Kernel 2: reduce partials -> sigma -> Newton-Schulz Sigma^{-1/2} -> fold
// weight/bias/mean into A = w*wm, beta = b - A*mean. 16 blocks x 256 threads.
// ---------------------------------------------------------------------------
__global__ __launch_bounds__(256, 1) void k_wm(const float* __restrict__ wgt,
                                               const float* __restrict__ bia) {
    const int g = blockIdx.x;
    const int t = threadIdx.x;
    const int r = t >> 4, c = t & 15;

    __shared__ float meanS[16];
    __shared__ float sig[16][17], P[16][17], T1[16][17], T2[16][17];

    float sv = 0.f;
    for (int b = 0; b < SLICES; b++) sv += g_sig[g][b][r][c];

    if (t < 16) {
        float a = 0.f;
        for (int b = 0; b < SLICES; b++) a += g_sum[g][b][t];
        meanS[t] = a * (1.0f / Mf);
    }
    __syncthreads();

    sv = sv * (1.0f / Mf) - meanS[r] * meanS[c] + ((r == c) ? EPSf : 0.f);
    sig[r][c] = sv;
    __syncthreads();

    float tr = 0.f;
#pragma unroll
    for (int k = 0; k < 16; k++) tr += sig[k][k];
    __syncthreads();

    sig[r][c] = sv / tr;                 // Sigma_N
    P[r][c] = (r == c) ? 1.f : 0.f;
    __syncthreads();

    for (int it = 0; it < 10; it++) {
        float d1 = 0.f;
#pragma unroll
        for (int k = 0; k < 16; k++) d1 += P[r][k] * P[k][c];
        T1[r][c] = d1;
        __syncthreads();
        float d2 = 0.f;
#pragma unroll
        for (int k = 0; k < 16; k++) d2 += T1[r][k] * P[k][c];
        T2[r][c] = d2;
        __syncthreads();
        float d3 = 0.f;
#pragma unroll
        for (int k = 0; k < 16; k++) d3 += T2[r][k] * sig[k][c];
        P[r][c] = 1.5f * P[r][c] - 0.5f * d3;
        __syncthreads();
    }

    const float wmv = P[r][c] * rsqrtf(tr);      // Sigma^{-1/2}
    const float Av  = wgt[g * 16 + r] * wmv;
    g_A[g][r][c] = Av;
    T1[r][c] = Av * meanS[c];
    __syncthreads();
    if (t < 16) {
        float acc = bia[g * 16 + t];
#pragma unroll
        for (int d = 0; d < 16; d++) acc -= T1[t][d];
        g_beta[g][t] = acc;
    }
}

// ---------------------------------------------------------------------------
// Kernel 3: apply out = A*v + beta. Persistent single-wave grid (296 blocks,
// 256 threads, occ 2) — measured-best configuration (~71 us).
// ---------------------------------------------------------------------------
__global__ __launch_bounds__(256, 2) void k_apply(const float* __restrict__ X,
                                                  float* __restrict__ Y) {
    __shared__ float As[Gg * 256];
    __shared__ float Bs[Gg * 16];

    for (int i = threadIdx.x; i < Gg * 256; i += 256)
        As[i] = ((const float*)g_A)[i];
    Bs[threadIdx.x] = ((const float*)g_beta)[threadIdx.x];
    __syncthreads();

    const int stride = APPLY_BLOCKS * 256;
    for (int t = blockIdx.x * 256 + threadIdx.x; t < TOT_TASKS; t += stride) {
        const int col = t / HW4;
        const int q   = t - col * HW4;
        const int g   = col & 15;
        const int n   = col >> 4;

        const size_t off = ((size_t)n * Cc + (size_t)g * 16) * HWs;
        const float4* xb = (const float4*)(X + off) + q;
        float4*       yb = (float4*)(Y + off) + q;
        const float*  Ag = As + g * 256;
        const float*  Bg = Bs + g * 16;

        float4 acc[16];
#pragma unroll
        for (int c = 0; c < 16; c++) {
            const float b = Bg[c];
            acc[c].x = b; acc[c].y = b; acc[c].z = b; acc[c].w = b;
        }

#pragma unroll
        for (int d = 0; d < 16; d++) {
            const float4 xv = xb[d * HW4];
#pragma unroll
            for (int c = 0; c < 16; c++) {
                const float w = Ag[c * 16 + d];
                acc[c].x = fmaf(w, xv.x, acc[c].x);
                acc[c].y = fmaf(w, xv.y, acc[c].y);
                acc[c].z = fmaf(w, xv.z, acc[c].z);
                acc[c].w = fmaf(w, xv.w, acc[c].w);
            }
        }
#pragma unroll
        for (int c = 0; c < 16; c++)
            yb[c * HW4] = acc[c];
    }
}

// ---------------------------------------------------------------------------
extern "C" void kernel_launch(void* const* d_in, const int* in_sizes, int n_in,
                              void* d_out, int out_size) {
    const float* X = (const float*)d_in[0];
    const float* W = (const float*)d_in[1];
    const float* B = (const float*)d_in[2];
    float* Y = (float*)d_out;

    k_stats<<<SLICES, 512>>>(X);
    k_wm<<<Gg, 256>>>(W, B);
    k_apply<<<APPLY_BLOCKS, 256>>>(X, Y);
}